// round 3
// baseline (speedup 1.0000x reference)
#include <cuda_runtime.h>
#include <cuda_bf16.h>

// Problem: B=8, S=512, D=512, MAX_LEN=512, fp32.
//
// scores[b,i,k] = sum_d Q[b,i,d]*K[b,k,d]  +  sum_m P[b,i,m]*E[m,k]
// where P[b,i,m] = Q[b,i,i-m] (1<=m<=i), P[b,i,0] = Q[b,i,i] + sum_{j>i} Q[b,i,j],
//       P[b,i,m]=0 for m>i.
// => one batched fp32 GEMM with effective K=1024 (two 512-chunk phases).

#define BATCH 8
#define SEQ   512
#define DM    512

// Scratch for P: 8*512*512 floats = 8.4 MB (device global => allocation-free).
__device__ float g_P[BATCH * SEQ * DM];

// ---------------------------------------------------------------------------
// Kernel 1: build P. One block per (b, i) row. 256 threads, row length 512.
// ---------------------------------------------------------------------------
__global__ __launch_bounds__(256) void build_P_kernel(const float* __restrict__ q) {
    const int i = blockIdx.x;
    const int b = blockIdx.y;
    const float* qr = q + ((size_t)(b * SEQ + i)) * DM;
    float* Pr = g_P + ((size_t)(b * SEQ + i)) * DM;

    __shared__ float sq[DM];
    __shared__ float red[256];

    const int t = threadIdx.x;
    float v0 = qr[t];
    float v1 = qr[t + 256];
    sq[t] = v0;
    sq[t + 256] = v1;

    // tail = sum over j > i of q[b,i,j]
    float s = 0.f;
    if (t > i)       s += v0;
    if (t + 256 > i) s += v1;
    red[t] = s;
    __syncthreads();
#pragma unroll
    for (int off = 128; off > 0; off >>= 1) {
        if (t < off) red[t] += red[t + off];
        __syncthreads();
    }
    const float tail = red[0];

#pragma unroll
    for (int h = 0; h < 2; ++h) {
        int m = t + h * 256;
        float val = (m <= i) ? sq[i - m] : 0.f;
        if (m == 0) val += tail;
        Pr[m] = val;
    }
}

// ---------------------------------------------------------------------------
// Kernel 2: fused batched GEMM with register-prefetch pipeline.
//   out[b] = Q[b] @ K[b]^T + P[b] @ E
// 128x128 tile / block, K-chunk 8, 256 threads, 8x8 per thread
// (4+4 split at stride 64 for conflict-free LDS.128). 128 chunks total:
// chunks 0..63 -> phase 0 (Q,K^T), chunks 64..127 -> phase 1 (P,E).
// ---------------------------------------------------------------------------
__global__ __launch_bounds__(256, 2) void fused_gemm_kernel(
    const float* __restrict__ Q, const float* __restrict__ K,
    const float* __restrict__ E, float* __restrict__ out)
{
    __shared__ float As[8][128];
    __shared__ float Bs[8][128];

    const int b    = blockIdx.z;
    const int row0 = blockIdx.y * 128;
    const int col0 = blockIdx.x * 128;

    const float* Qb = Q   + (size_t)b * SEQ * DM;
    const float* Kb = K   + (size_t)b * SEQ * DM;
    const float* Pb = g_P + (size_t)b * SEQ * DM;

    const int tid = threadIdx.x;
    const int tx  = tid & 15;   // output-col group
    const int ty  = tid >> 4;   // output-row group

    float acc[8][8];
#pragma unroll
    for (int r = 0; r < 8; ++r)
#pragma unroll
        for (int c = 0; c < 8; ++c) acc[r][c] = 0.f;

    // A/K loading: 128 rows x 8 k-cols; 256 threads x float4.
    const int a_row = tid >> 1;         // 0..127
    const int a_c4  = (tid & 1) << 2;   // 0 or 4
    // E loading: 8 rows x 128 cols; 256 threads x float4.
    const int e_row = tid >> 5;         // 0..7
    const int e_c4  = (tid & 31) << 2;  // 0..124

    const int NCHUNK = 128;

    // --- prefetch chunk 0 ---
    float4 av, bv;
    {
        av = *(const float4*)(Qb + (size_t)(row0 + a_row) * DM + a_c4);
        bv = *(const float4*)(Kb + (size_t)(col0 + a_row) * DM + a_c4);
    }

    for (int ks = 0; ks < NCHUNK; ++ks) {
        const int phase = ks >> 6;

        __syncthreads();   // previous chunk's compute done before overwrite
        As[a_c4 + 0][a_row] = av.x;
        As[a_c4 + 1][a_row] = av.y;
        As[a_c4 + 2][a_row] = av.z;
        As[a_c4 + 3][a_row] = av.w;
        if (phase == 0) {
            Bs[a_c4 + 0][a_row] = bv.x;
            Bs[a_c4 + 1][a_row] = bv.y;
            Bs[a_c4 + 2][a_row] = bv.z;
            Bs[a_c4 + 3][a_row] = bv.w;
        } else {
            *(float4*)&Bs[e_row][e_c4] = bv;
        }
        __syncthreads();

        // --- issue global loads for chunk ks+1 BEFORE the compute so the
        //     LDG latency is covered by ~512 FMAs/thread of this chunk ---
        float4 av_n, bv_n;
        if (ks + 1 < NCHUNK) {
            const int ksn    = ks + 1;
            const int phasen = ksn >> 6;
            const int k0n    = (ksn & 63) * 8;
            const float* An  = phasen ? Pb : Qb;
            av_n = *(const float4*)(An + (size_t)(row0 + a_row) * DM + k0n + a_c4);
            if (phasen == 0) {
                bv_n = *(const float4*)(Kb + (size_t)(col0 + a_row) * DM + k0n + a_c4);
            } else {
                bv_n = *(const float4*)(E + (size_t)(k0n + e_row) * DM + col0 + e_c4);
            }
        }

#pragma unroll
        for (int kk = 0; kk < 8; ++kk) {
            float a[8], bb[8];
            *(float4*)(a)      = *(const float4*)&As[kk][ty * 4];
            *(float4*)(a + 4)  = *(const float4*)&As[kk][ty * 4 + 64];
            *(float4*)(bb)     = *(const float4*)&Bs[kk][tx * 4];
            *(float4*)(bb + 4) = *(const float4*)&Bs[kk][tx * 4 + 64];
#pragma unroll
            for (int r = 0; r < 8; ++r)
#pragma unroll
                for (int c = 0; c < 8; ++c)
                    acc[r][c] = fmaf(a[r], bb[c], acc[r][c]);
        }

        av = av_n;
        bv = bv_n;
    }

    // Write 8x8 results: rows {ty*4+0..3, ty*4+64..67}, cols {tx*4+0..3, tx*4+64..67}
    float* ob = out + (size_t)b * SEQ * SEQ;
#pragma unroll
    for (int rg = 0; rg < 2; ++rg) {
#pragma unroll
        for (int r = 0; r < 4; ++r) {
            int row = row0 + ty * 4 + rg * 64 + r;
            float4 v0 = make_float4(acc[rg * 4 + r][0], acc[rg * 4 + r][1],
                                    acc[rg * 4 + r][2], acc[rg * 4 + r][3]);
            float4 v1 = make_float4(acc[rg * 4 + r][4], acc[rg * 4 + r][5],
                                    acc[rg * 4 + r][6], acc[rg * 4 + r][7]);
            *(float4*)(ob + (size_t)row * SEQ + col0 + tx * 4)      = v0;
            *(float4*)(ob + (size_t)row * SEQ + col0 + tx * 4 + 64) = v1;
        }
    }
}

// ---------------------------------------------------------------------------
extern "C" void kernel_launch(void* const* d_in, const int* in_sizes, int n_in,
                              void* d_out, int out_size) {
    const float* q = (const float*)d_in[0];
    const float* k = (const float*)d_in[1];
    const float* e = (const float*)d_in[2];
    float* out = (float*)d_out;

    (void)in_sizes; (void)n_in; (void)out_size;

    build_P_kernel<<<dim3(SEQ, BATCH), 256>>>(q);
    fused_gemm_kernel<<<dim3(SEQ / 128, SEQ / 128, BATCH), 256>>>(q, k, e, out);
}